// round 15
// baseline (speedup 1.0000x reference)
#include <cuda_runtime.h>
#include <cuda_fp16.h>
#include <math.h>
#include <stdint.h>

#define T_ 8192
#define D_ 1024
#define H_ 4096
#define E_ 8

#define BM 128
#define BN 128
#define BK 64
#define NT 256
#define STAGES 3
#define TILE_B (128 * 128)           // one 128x64 fp16 tile = 16384 bytes
#define STAGE_B (2 * TILE_B)         // A, B = 32768
#define SMEM_DYN (STAGES * STAGE_B)  // 98304

// prep kernel block ranges (route + w1 conversion only; w2 rides inside GEMM1)
#define NB_ROUTE 1024                // 8 tokens/block (route + direct x->fp16 scatter)
#define NB_W1    4096                // 8 rows/block (E*H = 32768 rows, K=1024)
#define NB_PREP  (NB_ROUTE + NB_W1)

// ---------------- static device scratch ----------------
__device__ int   g_cnt[E_];
__device__ int   g_tok[E_ * T_];          // expert slot -> token
__device__ __half g_xg[(size_t)E_ * T_ * D_];   // gathered x rows (fp16, duplicated)
__device__ __half g_w1[(size_t)E_ * H_ * D_];
__device__ __half g_w2[(size_t)E_ * D_ * H_];
__device__ __half g_h[(size_t)E_ * T_ * H_];

// ---------------- PTX helpers (generic sm_103-legal) ----------------
__device__ __forceinline__ uint32_t s2u(const void* p) {
    uint32_t a;
    asm("{ .reg .u64 t; cvta.to.shared.u64 t, %1; cvt.u32.u64 %0, t; }" : "=r"(a) : "l"(p));
    return a;
}
__device__ __forceinline__ void cpa16(uint32_t dst, const void* src) {
    asm volatile("cp.async.cg.shared.global [%0], [%1], 16;\n" :: "r"(dst), "l"(src) : "memory");
}
__device__ __forceinline__ void cpa_commit() { asm volatile("cp.async.commit_group;\n" ::: "memory"); }
template <int N> __device__ __forceinline__ void cpa_wait() {
    asm volatile("cp.async.wait_group %0;\n" :: "n"(N) : "memory");
}
__device__ __forceinline__ void ldsm_x4(uint32_t a, uint32_t& r0, uint32_t& r1, uint32_t& r2, uint32_t& r3) {
    asm volatile("ldmatrix.sync.aligned.m8n8.x4.shared.b16 {%0,%1,%2,%3}, [%4];"
                 : "=r"(r0), "=r"(r1), "=r"(r2), "=r"(r3) : "r"(a));
}
__device__ __forceinline__ void mma_f16(float* d, const uint32_t* a, const uint32_t* b) {
    asm volatile("mma.sync.aligned.m16n8k16.row.col.f32.f16.f16.f32 "
                 "{%0,%1,%2,%3}, {%4,%5,%6,%7}, {%8,%9}, {%0,%1,%2,%3};"
                 : "+f"(d[0]), "+f"(d[1]), "+f"(d[2]), "+f"(d[3])
                 : "r"(a[0]), "r"(a[1]), "r"(a[2]), "r"(a[3]), "r"(b[0]), "r"(b[1]));
}
// single-MUFU tanh for the swish epilogue
__device__ __forceinline__ float tanh_ap(float x) {
    float r;
    asm("tanh.approx.f32 %0, %1;" : "=f"(r) : "f"(x));
    return r;
}
// pack two fp32 -> fp16x2 (lo = a, hi = b), round-to-nearest
__device__ __forceinline__ uint32_t pack_h2(float lo, float hi) {
    uint32_t r;
    asm("cvt.rn.f16x2.f32 %0, %1, %2;" : "=r"(r) : "f"(hi), "f"(lo));
    return r;
}
// swizzled byte offset inside a Nx64 fp16 tile (rows of 128B, 16B chunks)
__device__ __forceinline__ uint32_t sw_off(int r, int c) {
    return (uint32_t)(r * 128 + ((c ^ (r & 7)) << 4));
}

// warp helper: weight-norm + fp16 quantize one row
__device__ __forceinline__ void wconv_row(const float* __restrict__ vrow, float gval,
                                          __half* __restrict__ orow, int K, int lane)
{
    const float4* p = (const float4*)vrow;
    float s = 0.f;
    int n4 = K >> 2;
    for (int i = lane; i < n4; i += 32) {
        float4 a = p[i];
        s += a.x * a.x + a.y * a.y + a.z * a.z + a.w * a.w;
    }
    #pragma unroll
    for (int o = 16; o; o >>= 1) s += __shfl_xor_sync(0xffffffffu, s, o);
    float scl = gval / fmaxf(sqrtf(s), 1e-12f);
    uint2* oh = (uint2*)orow;
    for (int i = lane; i < n4; i += 32) {
        float4 a = p[i];
        uint2 hp;
        hp.x = pack_h2(a.x * scl, a.y * scl);
        hp.y = pack_h2(a.z * scl, a.w * scl);
        oh[i] = hp;
    }
}

// ---------------- fused prep: route+scatter | wconv(w1) ----------------
__global__ __launch_bounds__(256) void prep_kernel(
    const float* __restrict__ x,
    const float* __restrict__ gate_v, const float* __restrict__ gate_g,
    const float* __restrict__ gate_b,
    const float* __restrict__ w1_v, const float* __restrict__ w1_g)
{
    const int b = blockIdx.x;
    const int tid = threadIdx.x;
    const int lane = tid & 31;
    const int warp = tid >> 5;

    if (b < NB_ROUTE) {
        // ---- routing + direct fp16 scatter: 1 warp per token, 8 tokens/block ----
        int t = b * 8 + warp;
        const float4* xp = (const float4*)(x + (size_t)t * D_);
        float4 xr[8];
        #pragma unroll
        for (int i = 0; i < 8; i++) xr[i] = xp[lane + 32 * i];
        float logit[E_], gnrm[E_];
        #pragma unroll
        for (int e = 0; e < E_; e++) {
            const float4* gp = (const float4*)(gate_v + (size_t)e * D_);
            float s = 0.f, q = 0.f;
            #pragma unroll
            for (int i = 0; i < 8; i++) {
                float4 g4 = gp[lane + 32 * i];
                s += xr[i].x * g4.x + xr[i].y * g4.y + xr[i].z * g4.z + xr[i].w * g4.w;
                q += g4.x * g4.x + g4.y * g4.y + g4.z * g4.z + g4.w * g4.w;
            }
            #pragma unroll
            for (int o = 16; o; o >>= 1) {
                s += __shfl_xor_sync(0xffffffffu, s, o);
                q += __shfl_xor_sync(0xffffffffu, q, o);
            }
            logit[e] = s;
            gnrm[e] = q;
        }
        int a0 = 0, a1 = 0;
        if (lane == 0) {
            int b0 = -1, b1i = -1;
            float v0 = -1e30f, v1 = -1e30f;
            #pragma unroll
            for (int e = 0; e < E_; e++) {
                float gs = gate_g[e] / fmaxf(sqrtf(gnrm[e]), 1e-12f);
                float l = logit[e] * gs + gate_b[e];
                if (l > v0)      { v1 = v0; b1i = b0; v0 = l; b0 = e; }
                else if (l > v1) { v1 = l; b1i = e; }
            }
            int e0 = min(b0, b1i), e1 = max(b0, b1i);
            int s0 = atomicAdd(&g_cnt[e0], 1);
            g_tok[e0 * T_ + s0] = t;
            a0 = e0 * T_ + s0;
            int s1 = atomicAdd(&g_cnt[e1], 1);
            g_tok[e1 * T_ + s1] = t;
            a1 = e1 * T_ + s1;
        }
        a0 = __shfl_sync(0xffffffffu, a0, 0);
        a1 = __shfl_sync(0xffffffffu, a1, 0);
        // all lanes: pack fp16 from registers and write both assignment rows
        uint2* d0 = (uint2*)(g_xg + (size_t)a0 * D_);
        uint2* d1 = (uint2*)(g_xg + (size_t)a1 * D_);
        #pragma unroll
        for (int i = 0; i < 8; i++) {
            uint2 hp;
            hp.x = pack_h2(xr[i].x, xr[i].y);
            hp.y = pack_h2(xr[i].z, xr[i].w);
            d0[lane + 32 * i] = hp;
            d1[lane + 32 * i] = hp;
        }
    } else {
        // ---- w1 weight-norm+convert: 8 rows/block, K = D_ ----
        int row = (b - NB_ROUTE) * 8 + warp;   // 0..E*H-1
        wconv_row(w1_v + (size_t)row * D_, w1_g[row], g_w1 + (size_t)row * D_, D_, lane);
    }
}

// ---------------- fp16 HMMA GEMM (CTA 128x128, 8 warps of 64x32, BK=64) ----------------
// FIRST: g_xg rows @ w1^T -> swish -> g_h (fp16); extra z-plane (z==E_) converts w2
// else : g_h rows @ w2^T -> + b2 -> atomicAdd into out (exactly 2 adds/elem, commutative)
template <int K, bool FIRST>
__global__ __launch_bounds__(NT, 2) void gemm_kernel(const float* __restrict__ bias,
                                                     float* __restrict__ out,
                                                     const float* __restrict__ w2_v,
                                                     const float* __restrict__ w2_g)
{
    const int tid  = threadIdx.x;
    const int lane = tid & 31;
    const int wid  = tid >> 5;

    if (FIRST && blockIdx.z == E_) {
        // overlap plane: w2 weight-norm+convert (E*D = 8192 rows, K = H_)
        // 2048 blocks (32 x 64), 4 rows/block handled by warps 0-3
        if (wid < 4) {
            int row = (blockIdx.y * gridDim.x + blockIdx.x) * 4 + wid;
            wconv_row(w2_v + (size_t)row * H_, w2_g[row], g_w2 + (size_t)row * H_, H_, lane);
        }
        return;
    }

    const int e   = blockIdx.z;
    const int cnt = g_cnt[e];
    const int m0  = blockIdx.y * BM;
    if (m0 >= cnt) return;
    const int n0  = blockIdx.x * BN;
    constexpr int NTOT = FIRST ? H_ : D_;
    constexpr int NC = K / BK;

    extern __shared__ char smem_raw[];
    __shared__ int s_tok[BM];
    const uint32_t sbase = s2u(smem_raw);
    const int wm   = (wid & 1) * 64;   // warp m offset in tile
    const int wn   = (wid >> 1) * 32;  // warp n offset in tile

    if (!FIRST) {
        if (tid < BM) {
            int m = m0 + tid;
            if (m >= cnt) m = cnt - 1;
            s_tok[tid] = g_tok[e * T_ + m];
        }
        __syncthreads();
    }

    const size_t arow = (size_t)(e * T_ + m0);
    const __half* A_g = (FIRST ? g_xg : g_h) + arow * K;
    const __half* B_g = (FIRST ? g_w1 : g_w2) + ((size_t)e * NTOT + n0) * K;

    auto load_chunk = [&](int c, int s) {
        uint32_t stg = sbase + s * STAGE_B;
        #pragma unroll
        for (int q = 0; q < 8; q++) {
            int i   = tid + q * NT;       // 0..2047
            int mtx = i >> 10;            // 0 A, 1 B
            int rem = i & 1023;
            int r   = rem >> 3;
            int cc  = rem & 7;
            const __half* src = (mtx == 0) ? A_g : B_g;
            src += (size_t)r * K + c * BK + cc * 8;
            cpa16(stg + mtx * TILE_B + sw_off(r, cc), src);
        }
    };

    float acc[4][4][4] = {};

    // prologue: stage first STAGES-1 chunks
    #pragma unroll
    for (int c = 0; c < STAGES - 1; ++c) { load_chunk(c, c); cpa_commit(); }

    int s = 0;
    for (int c = 0; c < NC; ++c) {
        cpa_wait<STAGES - 2>();
        __syncthreads();
        const int cn = c + STAGES - 1;
        if (cn < NC) {
            int sn = s + STAGES - 1;
            if (sn >= STAGES) sn -= STAGES;
            load_chunk(cn, sn);
        }
        cpa_commit();

        const uint32_t sA = sbase + s * STAGE_B;
        const uint32_t sB = sA + TILE_B;

        #pragma unroll
        for (int ks = 0; ks < 4; ++ks) {
            uint32_t ah[4][4], bh[4][2];
            const int ar = lane & 15;
            const int ac = ks * 2 + (lane >> 4);
            #pragma unroll
            for (int im = 0; im < 4; im++) {
                uint32_t off = sw_off(wm + im * 16 + ar, ac);
                ldsm_x4(sA + off, ah[im][0], ah[im][1], ah[im][2], ah[im][3]);
            }
            // B: one ldmatrix.x4 covers 2 n-frags (16 rows) for this k16
            const int br = (lane & 7) + ((lane >> 4) << 3);
            const int bc = ks * 2 + ((lane >> 3) & 1);
            #pragma unroll
            for (int half = 0; half < 2; half++) {
                uint32_t off = sw_off(wn + half * 16 + br, bc);
                ldsm_x4(sB + off, bh[2 * half][0], bh[2 * half][1],
                                  bh[2 * half + 1][0], bh[2 * half + 1][1]);
            }
            #pragma unroll
            for (int im = 0; im < 4; im++)
                #pragma unroll
                for (int in = 0; in < 4; in++)
                    mma_f16(acc[im][in], ah[im], bh[in]);
        }
        if (++s == STAGES) s = 0;
    }

    // epilogue: hoist the 8 distinct bias values per thread into registers
    float bs0[4], bs1[4];
    #pragma unroll
    for (int in = 0; in < 4; in++) {
        const int col = n0 + wn + in * 8 + 2 * (lane & 3);
        bs0[in] = bias[(size_t)e * NTOT + col];
        bs1[in] = bias[(size_t)e * NTOT + col + 1];
    }
    const int lrow = wm + (lane >> 2);
    #pragma unroll
    for (int im = 0; im < 4; im++) {
        #pragma unroll
        for (int half = 0; half < 2; half++) {
            const int lr = lrow + im * 16 + half * 8;
            const int mg = m0 + lr;
            if (mg >= cnt) continue;
            #pragma unroll
            for (int in = 0; in < 4; in++) {
                const int col = n0 + wn + in * 8 + 2 * (lane & 3);
                float z0 = acc[im][in][2 * half]     + bs0[in];
                float z1 = acc[im][in][2 * half + 1] + bs1[in];
                if (FIRST) {
                    // swish via single-MUFU tanh: z*sigmoid(z) = z*(0.5*tanh(z/2)+0.5)
                    float w0 = z0 * (0.5f * tanh_ap(0.5f * z0) + 0.5f);
                    float w1 = z1 * (0.5f * tanh_ap(0.5f * z1) + 0.5f);
                    size_t o = ((size_t)(e * T_) + mg) * H_ + col;
                    *(uint32_t*)(g_h + o) = pack_h2(w0, w1);
                } else {
                    size_t o = (size_t)s_tok[lr] * D_ + col;
                    atomicAdd(out + o,     z0);
                    atomicAdd(out + o + 1, z1);
                }
            }
        }
    }
}

// ---------------- launch ----------------
extern "C" void kernel_launch(void* const* d_in, const int* in_sizes, int n_in,
                              void* d_out, int out_size)
{
    const float* x      = (const float*)d_in[0];
    const float* gate_v = (const float*)d_in[1];
    const float* gate_g = (const float*)d_in[2];
    const float* gate_b = (const float*)d_in[3];
    const float* w1_v   = (const float*)d_in[4];
    const float* w1_g   = (const float*)d_in[5];
    const float* b1     = (const float*)d_in[6];
    const float* w2_v   = (const float*)d_in[7];
    const float* w2_g   = (const float*)d_in[8];
    const float* b2     = (const float*)d_in[9];
    float* out = (float*)d_out;

    cudaFuncSetAttribute(gemm_kernel<D_, true>,  cudaFuncAttributeMaxDynamicSharedMemorySize, SMEM_DYN);
    cudaFuncSetAttribute(gemm_kernel<H_, false>, cudaFuncAttributeMaxDynamicSharedMemorySize, SMEM_DYN);

    void* cnt_addr = nullptr;
    cudaGetSymbolAddress(&cnt_addr, g_cnt);
    cudaMemsetAsync(cnt_addr, 0, E_ * sizeof(int));
    cudaMemsetAsync(out, 0, (size_t)out_size * sizeof(float));

    prep_kernel<<<NB_PREP, 256>>>(x, gate_v, gate_g, gate_b, w1_v, w1_g);

    // GEMM1 with an extra z-plane that converts w2 in its DRAM shadow
    gemm_kernel<D_, true><<<dim3(H_ / BN, T_ / BM, E_ + 1), NT, SMEM_DYN>>>(b1, out, w2_v, w2_g);
    gemm_kernel<H_, false><<<dim3(D_ / BN, T_ / BM, E_), NT, SMEM_DYN>>>(b2, out, nullptr, nullptr);
}

// round 16
// speedup vs baseline: 1.0313x; 1.0313x over previous
#include <cuda_runtime.h>
#include <cuda_fp16.h>
#include <math.h>
#include <stdint.h>

#define T_ 8192
#define D_ 1024
#define H_ 4096
#define E_ 8

#define BM 128
#define BN 128
#define BK 64
#define NT 256
#define STAGES 3
#define TILE_B (128 * 128)           // one 128x64 fp16 tile = 16384 bytes
#define STAGE_B (2 * TILE_B)         // A, B = 32768
#define SMEM_DYN (STAGES * STAGE_B)  // 98304

// prep kernel block ranges
#define NB_ROUTE 1024                // 8 tokens/block (route + fp16 scatter)
#define NB_W1    4096                // 8 rows/block (E*H = 32768 rows, K=1024)
#define NB_W2    1024                // 8 rows/block (E*D = 8192 rows,  K=4096)
#define NB_PREP  (NB_ROUTE + NB_W1 + NB_W2)

// ---------------- static device scratch ----------------
__device__ int   g_cnt[E_];
__device__ int   g_tok[E_ * T_];          // expert slot -> token
__device__ __half g_xg[(size_t)E_ * T_ * D_];   // gathered x rows (fp16, duplicated)
__device__ __half g_w1[(size_t)E_ * H_ * D_];
__device__ __half g_w2[(size_t)E_ * D_ * H_];
__device__ __half g_h[(size_t)E_ * T_ * H_];

// ---------------- PTX helpers (generic sm_103-legal) ----------------
__device__ __forceinline__ uint32_t s2u(const void* p) {
    uint32_t a;
    asm("{ .reg .u64 t; cvta.to.shared.u64 t, %1; cvt.u32.u64 %0, t; }" : "=r"(a) : "l"(p));
    return a;
}
__device__ __forceinline__ void cpa16(uint32_t dst, const void* src) {
    asm volatile("cp.async.cg.shared.global [%0], [%1], 16;\n" :: "r"(dst), "l"(src) : "memory");
}
__device__ __forceinline__ void cpa_commit() { asm volatile("cp.async.commit_group;\n" ::: "memory"); }
template <int N> __device__ __forceinline__ void cpa_wait() {
    asm volatile("cp.async.wait_group %0;\n" :: "n"(N) : "memory");
}
__device__ __forceinline__ void ldsm_x4(uint32_t a, uint32_t& r0, uint32_t& r1, uint32_t& r2, uint32_t& r3) {
    asm volatile("ldmatrix.sync.aligned.m8n8.x4.shared.b16 {%0,%1,%2,%3}, [%4];"
                 : "=r"(r0), "=r"(r1), "=r"(r2), "=r"(r3) : "r"(a));
}
__device__ __forceinline__ void mma_f16(float* d, const uint32_t* a, const uint32_t* b) {
    asm volatile("mma.sync.aligned.m16n8k16.row.col.f32.f16.f16.f32 "
                 "{%0,%1,%2,%3}, {%4,%5,%6,%7}, {%8,%9}, {%0,%1,%2,%3};"
                 : "+f"(d[0]), "+f"(d[1]), "+f"(d[2]), "+f"(d[3])
                 : "r"(a[0]), "r"(a[1]), "r"(a[2]), "r"(a[3]), "r"(b[0]), "r"(b[1]));
}
// single-MUFU tanh for the swish epilogue
__device__ __forceinline__ float tanh_ap(float x) {
    float r;
    asm("tanh.approx.f32 %0, %1;" : "=f"(r) : "f"(x));
    return r;
}
// pack two fp32 -> fp16x2 (lo = a, hi = b), round-to-nearest
__device__ __forceinline__ uint32_t pack_h2(float lo, float hi) {
    uint32_t r;
    asm("cvt.rn.f16x2.f32 %0, %1, %2;" : "=r"(r) : "f"(hi), "f"(lo));
    return r;
}
// swizzled byte offset inside a Nx64 fp16 tile (rows of 128B, 16B chunks)
__device__ __forceinline__ uint32_t sw_off(int r, int c) {
    return (uint32_t)(r * 128 + ((c ^ (r & 7)) << 4));
}

// warp helper: weight-norm + fp16 quantize one row
__device__ __forceinline__ void wconv_row(const float* __restrict__ vrow, float gval,
                                          __half* __restrict__ orow, int K, int lane)
{
    const float4* p = (const float4*)vrow;
    float s = 0.f;
    int n4 = K >> 2;
    for (int i = lane; i < n4; i += 32) {
        float4 a = p[i];
        s += a.x * a.x + a.y * a.y + a.z * a.z + a.w * a.w;
    }
    #pragma unroll
    for (int o = 16; o; o >>= 1) s += __shfl_xor_sync(0xffffffffu, s, o);
    float scl = gval / fmaxf(sqrtf(s), 1e-12f);
    uint2* oh = (uint2*)orow;
    for (int i = lane; i < n4; i += 32) {
        float4 a = p[i];
        uint2 hp;
        hp.x = pack_h2(a.x * scl, a.y * scl);
        hp.y = pack_h2(a.z * scl, a.w * scl);
        oh[i] = hp;
    }
}

// ---------------- fused prep: route+scatter | wconv(w1) | wconv(w2) ----------------
__global__ __launch_bounds__(256) void prep_kernel(
    const float* __restrict__ x,
    const float* __restrict__ gate_v, const float* __restrict__ gate_g,
    const float* __restrict__ gate_b,
    const float* __restrict__ w1_v, const float* __restrict__ w1_g,
    const float* __restrict__ w2_v, const float* __restrict__ w2_g)
{
    const int b = blockIdx.x;
    const int tid = threadIdx.x;
    const int lane = tid & 31;
    const int warp = tid >> 5;

    if (b < NB_ROUTE) {
        // ---- routing: low-register streaming form (no x array held live) ----
        int t = b * 8 + warp;
        const float4* xp = (const float4*)(x + (size_t)t * D_);
        float logit[E_] = {}, gnrm[E_] = {};
        for (int i = 0; i < 8; i++) {
            float4 xv = xp[lane + 32 * i];
            #pragma unroll
            for (int e = 0; e < E_; e++) {
                float4 g4 = ((const float4*)(gate_v + (size_t)e * D_))[lane + 32 * i];
                logit[e] += xv.x * g4.x + xv.y * g4.y + xv.z * g4.z + xv.w * g4.w;
                gnrm[e]  += g4.x * g4.x + g4.y * g4.y + g4.z * g4.z + g4.w * g4.w;
            }
        }
        #pragma unroll
        for (int e = 0; e < E_; e++) {
            #pragma unroll
            for (int o = 16; o; o >>= 1) {
                logit[e] += __shfl_xor_sync(0xffffffffu, logit[e], o);
                gnrm[e]  += __shfl_xor_sync(0xffffffffu, gnrm[e], o);
            }
        }
        int a0 = 0, a1 = 0;
        if (lane == 0) {
            int b0 = -1, b1i = -1;
            float v0 = -1e30f, v1 = -1e30f;
            #pragma unroll
            for (int e = 0; e < E_; e++) {
                float gs = gate_g[e] / fmaxf(sqrtf(gnrm[e]), 1e-12f);
                float l = logit[e] * gs + gate_b[e];
                if (l > v0)      { v1 = v0; b1i = b0; v0 = l; b0 = e; }
                else if (l > v1) { v1 = l; b1i = e; }
            }
            int e0 = min(b0, b1i), e1 = max(b0, b1i);
            int s0 = atomicAdd(&g_cnt[e0], 1);
            g_tok[e0 * T_ + s0] = t;
            a0 = e0 * T_ + s0;
            int s1 = atomicAdd(&g_cnt[e1], 1);
            g_tok[e1 * T_ + s1] = t;
            a1 = e1 * T_ + s1;
        }
        a0 = __shfl_sync(0xffffffffu, a0, 0);
        a1 = __shfl_sync(0xffffffffu, a1, 0);
        // scatter: re-read x (L2-hot) and write both assignment rows as fp16
        uint2* d0 = (uint2*)(g_xg + (size_t)a0 * D_);
        uint2* d1 = (uint2*)(g_xg + (size_t)a1 * D_);
        for (int i = 0; i < 8; i++) {
            float4 xv = xp[lane + 32 * i];
            uint2 hp;
            hp.x = pack_h2(xv.x, xv.y);
            hp.y = pack_h2(xv.z, xv.w);
            d0[lane + 32 * i] = hp;
            d1[lane + 32 * i] = hp;
        }
    } else if (b < NB_ROUTE + NB_W1) {
        // ---- w1 weight-norm+convert: 8 rows/block, K = D_ ----
        int row = (b - NB_ROUTE) * 8 + warp;   // 0..E*H-1
        wconv_row(w1_v + (size_t)row * D_, w1_g[row], g_w1 + (size_t)row * D_, D_, lane);
    } else {
        // ---- w2 weight-norm+convert: 8 rows/block, K = H_ ----
        int row = (b - NB_ROUTE - NB_W1) * 8 + warp;   // 0..E*D-1
        wconv_row(w2_v + (size_t)row * H_, w2_g[row], g_w2 + (size_t)row * H_, H_, lane);
    }
}

// ---------------- fp16 HMMA GEMM (CTA 128x128, 8 warps of 64x32, BK=64) ----------------
// FIRST: g_xg rows @ w1^T -> swish -> g_h (fp16)
// else : g_h rows @ w2^T -> + b2 -> atomicAdd into out (exactly 2 adds/elem, commutative)
template <int K, bool FIRST>
__global__ __launch_bounds__(NT, 2) void gemm_kernel(const float* __restrict__ bias,
                                                     float* __restrict__ out)
{
    const int e   = blockIdx.z;
    const int cnt = g_cnt[e];
    const int m0  = blockIdx.y * BM;
    if (m0 >= cnt) return;
    const int n0  = blockIdx.x * BN;
    constexpr int NTOT = FIRST ? H_ : D_;
    constexpr int NC = K / BK;

    extern __shared__ char smem_raw[];
    __shared__ int s_tok[BM];
    const uint32_t sbase = s2u(smem_raw);
    const int tid  = threadIdx.x;
    const int lane = tid & 31;
    const int wid  = tid >> 5;
    const int wm   = (wid & 1) * 64;   // warp m offset in tile
    const int wn   = (wid >> 1) * 32;  // warp n offset in tile

    if (!FIRST) {
        if (tid < BM) {
            int m = m0 + tid;
            if (m >= cnt) m = cnt - 1;
            s_tok[tid] = g_tok[e * T_ + m];
        }
        __syncthreads();
    }

    const size_t arow = (size_t)(e * T_ + m0);
    const __half* A_g = (FIRST ? g_xg : g_h) + arow * K;
    const __half* B_g = (FIRST ? g_w1 : g_w2) + ((size_t)e * NTOT + n0) * K;

    auto load_chunk = [&](int c, int s) {
        uint32_t stg = sbase + s * STAGE_B;
        #pragma unroll
        for (int q = 0; q < 8; q++) {
            int i   = tid + q * NT;       // 0..2047
            int mtx = i >> 10;            // 0 A, 1 B
            int rem = i & 1023;
            int r   = rem >> 3;
            int cc  = rem & 7;
            const __half* src = (mtx == 0) ? A_g : B_g;
            src += (size_t)r * K + c * BK + cc * 8;
            cpa16(stg + mtx * TILE_B + sw_off(r, cc), src);
        }
    };

    float acc[4][4][4] = {};

    // prologue: stage first STAGES-1 chunks
    #pragma unroll
    for (int c = 0; c < STAGES - 1; ++c) { load_chunk(c, c); cpa_commit(); }

    int s = 0;
    for (int c = 0; c < NC; ++c) {
        cpa_wait<STAGES - 2>();
        __syncthreads();
        const int cn = c + STAGES - 1;
        if (cn < NC) {
            int sn = s + STAGES - 1;
            if (sn >= STAGES) sn -= STAGES;
            load_chunk(cn, sn);
        }
        cpa_commit();

        const uint32_t sA = sbase + s * STAGE_B;
        const uint32_t sB = sA + TILE_B;

        #pragma unroll
        for (int ks = 0; ks < 4; ++ks) {
            uint32_t ah[4][4], bh[4][2];
            const int ar = lane & 15;
            const int ac = ks * 2 + (lane >> 4);
            #pragma unroll
            for (int im = 0; im < 4; im++) {
                uint32_t off = sw_off(wm + im * 16 + ar, ac);
                ldsm_x4(sA + off, ah[im][0], ah[im][1], ah[im][2], ah[im][3]);
            }
            // B: one ldmatrix.x4 covers 2 n-frags (16 rows) for this k16
            const int br = (lane & 7) + ((lane >> 4) << 3);
            const int bc = ks * 2 + ((lane >> 3) & 1);
            #pragma unroll
            for (int half = 0; half < 2; half++) {
                uint32_t off = sw_off(wn + half * 16 + br, bc);
                ldsm_x4(sB + off, bh[2 * half][0], bh[2 * half][1],
                                  bh[2 * half + 1][0], bh[2 * half + 1][1]);
            }
            #pragma unroll
            for (int im = 0; im < 4; im++)
                #pragma unroll
                for (int in = 0; in < 4; in++)
                    mma_f16(acc[im][in], ah[im], bh[in]);
        }
        if (++s == STAGES) s = 0;
    }

    // epilogue: hoist the 8 distinct bias values per thread into registers
    float bs0[4], bs1[4];
    #pragma unroll
    for (int in = 0; in < 4; in++) {
        const int col = n0 + wn + in * 8 + 2 * (lane & 3);
        bs0[in] = bias[(size_t)e * NTOT + col];
        bs1[in] = bias[(size_t)e * NTOT + col + 1];
    }
    const int lrow = wm + (lane >> 2);
    #pragma unroll
    for (int im = 0; im < 4; im++) {
        #pragma unroll
        for (int half = 0; half < 2; half++) {
            const int lr = lrow + im * 16 + half * 8;
            const int mg = m0 + lr;
            if (mg >= cnt) continue;
            #pragma unroll
            for (int in = 0; in < 4; in++) {
                const int col = n0 + wn + in * 8 + 2 * (lane & 3);
                float z0 = acc[im][in][2 * half]     + bs0[in];
                float z1 = acc[im][in][2 * half + 1] + bs1[in];
                if (FIRST) {
                    // swish via single-MUFU tanh: z*sigmoid(z) = z*(0.5*tanh(z/2)+0.5)
                    float w0 = z0 * (0.5f * tanh_ap(0.5f * z0) + 0.5f);
                    float w1 = z1 * (0.5f * tanh_ap(0.5f * z1) + 0.5f);
                    size_t o = ((size_t)(e * T_) + mg) * H_ + col;
                    *(uint32_t*)(g_h + o) = pack_h2(w0, w1);
                } else {
                    size_t o = (size_t)s_tok[lr] * D_ + col;
                    atomicAdd(out + o,     z0);
                    atomicAdd(out + o + 1, z1);
                }
            }
        }
    }
}

// ---------------- launch ----------------
extern "C" void kernel_launch(void* const* d_in, const int* in_sizes, int n_in,
                              void* d_out, int out_size)
{
    const float* x      = (const float*)d_in[0];
    const float* gate_v = (const float*)d_in[1];
    const float* gate_g = (const float*)d_in[2];
    const float* gate_b = (const float*)d_in[3];
    const float* w1_v   = (const float*)d_in[4];
    const float* w1_g   = (const float*)d_in[5];
    const float* b1     = (const float*)d_in[6];
    const float* w2_v   = (const float*)d_in[7];
    const float* w2_g   = (const float*)d_in[8];
    const float* b2     = (const float*)d_in[9];
    float* out = (float*)d_out;

    cudaFuncSetAttribute(gemm_kernel<D_, true>,  cudaFuncAttributeMaxDynamicSharedMemorySize, SMEM_DYN);
    cudaFuncSetAttribute(gemm_kernel<H_, false>, cudaFuncAttributeMaxDynamicSharedMemorySize, SMEM_DYN);

    void* cnt_addr = nullptr;
    cudaGetSymbolAddress(&cnt_addr, g_cnt);
    cudaMemsetAsync(cnt_addr, 0, E_ * sizeof(int));
    cudaMemsetAsync(out, 0, (size_t)out_size * sizeof(float));

    prep_kernel<<<NB_PREP, 256>>>(x, gate_v, gate_g, gate_b, w1_v, w1_g, w2_v, w2_g);

    gemm_kernel<D_, true><<<dim3(H_ / BN, T_ / BM, E_), NT, SMEM_DYN>>>(b1, out);
    gemm_kernel<H_, false><<<dim3(D_ / BN, T_ / BM, E_), NT, SMEM_DYN>>>(b2, out);
}

// round 17
// speedup vs baseline: 1.0423x; 1.0107x over previous
#include <cuda_runtime.h>
#include <cuda_fp16.h>
#include <math.h>
#include <stdint.h>

#define T_ 8192
#define D_ 1024
#define H_ 4096
#define E_ 8

#define BM 128
#define BN 128
#define BK 64
#define NT 256
#define STAGES 3
#define TILE_B (128 * 128)           // one 128x64 fp16 tile = 16384 bytes
#define STAGE_B (2 * TILE_B)         // A, B = 32768
#define SMEM_DYN (STAGES * STAGE_B)  // 98304

// prep kernel block ranges (w1 first, w2 second, route last -> short tail)
#define NB_W1    4096                // 8 rows/block (E*H = 32768 rows, K=1024)
#define NB_W2    1024                // 8 rows/block (E*D = 8192 rows,  K=4096)
#define NB_ROUTE 1024                // 8 tokens/block (route + fp16 scatter)
#define NB_PREP  (NB_W1 + NB_W2 + NB_ROUTE)

// ---------------- static device scratch ----------------
__device__ int   g_cnt[E_];
__device__ int   g_tok[E_ * T_];          // expert slot -> token
__device__ __half g_xg[(size_t)E_ * T_ * D_];   // gathered x rows (fp16, duplicated)
__device__ __half g_w1[(size_t)E_ * H_ * D_];
__device__ __half g_w2[(size_t)E_ * D_ * H_];
__device__ __half g_h[(size_t)E_ * T_ * H_];

// ---------------- PTX helpers (generic sm_103-legal) ----------------
__device__ __forceinline__ uint32_t s2u(const void* p) {
    uint32_t a;
    asm("{ .reg .u64 t; cvta.to.shared.u64 t, %1; cvt.u32.u64 %0, t; }" : "=r"(a) : "l"(p));
    return a;
}
__device__ __forceinline__ void cpa16(uint32_t dst, const void* src) {
    asm volatile("cp.async.cg.shared.global [%0], [%1], 16;\n" :: "r"(dst), "l"(src) : "memory");
}
__device__ __forceinline__ void cpa_commit() { asm volatile("cp.async.commit_group;\n" ::: "memory"); }
template <int N> __device__ __forceinline__ void cpa_wait() {
    asm volatile("cp.async.wait_group %0;\n" :: "n"(N) : "memory");
}
__device__ __forceinline__ void ldsm_x4(uint32_t a, uint32_t& r0, uint32_t& r1, uint32_t& r2, uint32_t& r3) {
    asm volatile("ldmatrix.sync.aligned.m8n8.x4.shared.b16 {%0,%1,%2,%3}, [%4];"
                 : "=r"(r0), "=r"(r1), "=r"(r2), "=r"(r3) : "r"(a));
}
__device__ __forceinline__ void mma_f16(float* d, const uint32_t* a, const uint32_t* b) {
    asm volatile("mma.sync.aligned.m16n8k16.row.col.f32.f16.f16.f32 "
                 "{%0,%1,%2,%3}, {%4,%5,%6,%7}, {%8,%9}, {%0,%1,%2,%3};"
                 : "+f"(d[0]), "+f"(d[1]), "+f"(d[2]), "+f"(d[3])
                 : "r"(a[0]), "r"(a[1]), "r"(a[2]), "r"(a[3]), "r"(b[0]), "r"(b[1]));
}
// single-MUFU tanh for the swish epilogue
__device__ __forceinline__ float tanh_ap(float x) {
    float r;
    asm("tanh.approx.f32 %0, %1;" : "=f"(r) : "f"(x));
    return r;
}
// pack two fp32 -> fp16x2 (lo = a, hi = b), round-to-nearest
__device__ __forceinline__ uint32_t pack_h2(float lo, float hi) {
    uint32_t r;
    asm("cvt.rn.f16x2.f32 %0, %1, %2;" : "=r"(r) : "f"(hi), "f"(lo));
    return r;
}
// swizzled byte offset inside a Nx64 fp16 tile (rows of 128B, 16B chunks)
__device__ __forceinline__ uint32_t sw_off(int r, int c) {
    return (uint32_t)(r * 128 + ((c ^ (r & 7)) << 4));
}

// warp helper: weight-norm + fp16 quantize one row (4x unrolled for MLP)
__device__ __forceinline__ void wconv_row(const float* __restrict__ vrow, float gval,
                                          __half* __restrict__ orow, int K, int lane)
{
    const float4* p = (const float4*)vrow;
    int n4 = K >> 2;
    float s0 = 0.f, s1 = 0.f, s2 = 0.f, s3 = 0.f;
    for (int i = lane; i < n4; i += 128) {
        float4 a0 = p[i];
        float4 a1 = p[i + 32];
        float4 a2 = p[i + 64];
        float4 a3 = p[i + 96];
        s0 += a0.x * a0.x + a0.y * a0.y + a0.z * a0.z + a0.w * a0.w;
        s1 += a1.x * a1.x + a1.y * a1.y + a1.z * a1.z + a1.w * a1.w;
        s2 += a2.x * a2.x + a2.y * a2.y + a2.z * a2.z + a2.w * a2.w;
        s3 += a3.x * a3.x + a3.y * a3.y + a3.z * a3.z + a3.w * a3.w;
    }
    float s = (s0 + s1) + (s2 + s3);
    #pragma unroll
    for (int o = 16; o; o >>= 1) s += __shfl_xor_sync(0xffffffffu, s, o);
    float scl = gval / fmaxf(sqrtf(s), 1e-12f);
    uint2* oh = (uint2*)orow;
    for (int i = lane; i < n4; i += 128) {
        float4 a0 = p[i];
        float4 a1 = p[i + 32];
        float4 a2 = p[i + 64];
        float4 a3 = p[i + 96];
        uint2 h0, h1, h2, h3;
        h0.x = pack_h2(a0.x * scl, a0.y * scl); h0.y = pack_h2(a0.z * scl, a0.w * scl);
        h1.x = pack_h2(a1.x * scl, a1.y * scl); h1.y = pack_h2(a1.z * scl, a1.w * scl);
        h2.x = pack_h2(a2.x * scl, a2.y * scl); h2.y = pack_h2(a2.z * scl, a2.w * scl);
        h3.x = pack_h2(a3.x * scl, a3.y * scl); h3.y = pack_h2(a3.z * scl, a3.w * scl);
        oh[i]      = h0;
        oh[i + 32] = h1;
        oh[i + 64] = h2;
        oh[i + 96] = h3;
    }
}

// ---------------- fused prep: wconv(w1) | wconv(w2) | route+scatter ----------------
__global__ __launch_bounds__(256) void prep_kernel(
    const float* __restrict__ x,
    const float* __restrict__ gate_v, const float* __restrict__ gate_g,
    const float* __restrict__ gate_b,
    const float* __restrict__ w1_v, const float* __restrict__ w1_g,
    const float* __restrict__ w2_v, const float* __restrict__ w2_g)
{
    const int b = blockIdx.x;
    const int tid = threadIdx.x;
    const int lane = tid & 31;
    const int warp = tid >> 5;

    if (b < NB_W1) {
        // ---- w1 weight-norm+convert: 8 rows/block, K = D_ (n4=256, unroll covers 2 iters) ----
        int row = b * 8 + warp;   // 0..E*H-1
        wconv_row(w1_v + (size_t)row * D_, w1_g[row], g_w1 + (size_t)row * D_, D_, lane);
    } else if (b < NB_W1 + NB_W2) {
        // ---- w2 weight-norm+convert: 8 rows/block, K = H_ ----
        int row = (b - NB_W1) * 8 + warp;   // 0..E*D-1
        wconv_row(w2_v + (size_t)row * H_, w2_g[row], g_w2 + (size_t)row * H_, H_, lane);
    } else {
        // ---- routing: low-register streaming form ----
        int t = (b - NB_W1 - NB_W2) * 8 + warp;
        const float4* xp = (const float4*)(x + (size_t)t * D_);
        float logit[E_] = {}, gnrm[E_] = {};
        #pragma unroll
        for (int i = 0; i < 8; i++) {
            float4 xv = xp[lane + 32 * i];
            #pragma unroll
            for (int e = 0; e < E_; e++) {
                float4 g4 = ((const float4*)(gate_v + (size_t)e * D_))[lane + 32 * i];
                logit[e] += xv.x * g4.x + xv.y * g4.y + xv.z * g4.z + xv.w * g4.w;
                gnrm[e]  += g4.x * g4.x + g4.y * g4.y + g4.z * g4.z + g4.w * g4.w;
            }
        }
        #pragma unroll
        for (int e = 0; e < E_; e++) {
            #pragma unroll
            for (int o = 16; o; o >>= 1) {
                logit[e] += __shfl_xor_sync(0xffffffffu, logit[e], o);
                gnrm[e]  += __shfl_xor_sync(0xffffffffu, gnrm[e], o);
            }
        }
        int a0 = 0, a1 = 0;
        if (lane == 0) {
            int b0 = -1, b1i = -1;
            float v0 = -1e30f, v1 = -1e30f;
            #pragma unroll
            for (int e = 0; e < E_; e++) {
                float gs = gate_g[e] / fmaxf(sqrtf(gnrm[e]), 1e-12f);
                float l = logit[e] * gs + gate_b[e];
                if (l > v0)      { v1 = v0; b1i = b0; v0 = l; b0 = e; }
                else if (l > v1) { v1 = l; b1i = e; }
            }
            int e0 = min(b0, b1i), e1 = max(b0, b1i);
            int s0 = atomicAdd(&g_cnt[e0], 1);
            g_tok[e0 * T_ + s0] = t;
            a0 = e0 * T_ + s0;
            int s1 = atomicAdd(&g_cnt[e1], 1);
            g_tok[e1 * T_ + s1] = t;
            a1 = e1 * T_ + s1;
        }
        a0 = __shfl_sync(0xffffffffu, a0, 0);
        a1 = __shfl_sync(0xffffffffu, a1, 0);
        // scatter: re-read x (L2-hot) and write both assignment rows as fp16
        uint2* d0 = (uint2*)(g_xg + (size_t)a0 * D_);
        uint2* d1 = (uint2*)(g_xg + (size_t)a1 * D_);
        #pragma unroll
        for (int i = 0; i < 8; i++) {
            float4 xv = xp[lane + 32 * i];
            uint2 hp;
            hp.x = pack_h2(xv.x, xv.y);
            hp.y = pack_h2(xv.z, xv.w);
            d0[lane + 32 * i] = hp;
            d1[lane + 32 * i] = hp;
        }
    }
}

// ---------------- fp16 HMMA GEMM (CTA 128x128, 8 warps of 64x32, BK=64) ----------------
// FIRST: g_xg rows @ w1^T -> swish -> g_h (fp16)
// else : g_h rows @ w2^T -> + b2 -> atomicAdd into out (exactly 2 adds/elem, commutative)
template <int K, bool FIRST>
__global__ __launch_bounds__(NT, 2) void gemm_kernel(const float* __restrict__ bias,
                                                     float* __restrict__ out)
{
    const int e   = blockIdx.z;
    const int cnt = g_cnt[e];
    const int m0  = blockIdx.y * BM;
    if (m0 >= cnt) return;
    const int n0  = blockIdx.x * BN;
    constexpr int NTOT = FIRST ? H_ : D_;
    constexpr int NC = K / BK;

    extern __shared__ char smem_raw[];
    __shared__ int s_tok[BM];
    const uint32_t sbase = s2u(smem_raw);
    const int tid  = threadIdx.x;
    const int lane = tid & 31;
    const int wid  = tid >> 5;
    const int wm   = (wid & 1) * 64;   // warp m offset in tile
    const int wn   = (wid >> 1) * 32;  // warp n offset in tile

    if (!FIRST) {
        if (tid < BM) {
            int m = m0 + tid;
            if (m >= cnt) m = cnt - 1;
            s_tok[tid] = g_tok[e * T_ + m];
        }
        __syncthreads();
    }

    const size_t arow = (size_t)(e * T_ + m0);
    const __half* A_g = (FIRST ? g_xg : g_h) + arow * K;
    const __half* B_g = (FIRST ? g_w1 : g_w2) + ((size_t)e * NTOT + n0) * K;

    auto load_chunk = [&](int c, int s) {
        uint32_t stg = sbase + s * STAGE_B;
        #pragma unroll
        for (int q = 0; q < 8; q++) {
            int i   = tid + q * NT;       // 0..2047
            int mtx = i >> 10;            // 0 A, 1 B
            int rem = i & 1023;
            int r   = rem >> 3;
            int cc  = rem & 7;
            const __half* src = (mtx == 0) ? A_g : B_g;
            src += (size_t)r * K + c * BK + cc * 8;
            cpa16(stg + mtx * TILE_B + sw_off(r, cc), src);
        }
    };

    float acc[4][4][4] = {};

    // prologue: stage first STAGES-1 chunks
    #pragma unroll
    for (int c = 0; c < STAGES - 1; ++c) { load_chunk(c, c); cpa_commit(); }

    int s = 0;
    for (int c = 0; c < NC; ++c) {
        cpa_wait<STAGES - 2>();
        __syncthreads();
        const int cn = c + STAGES - 1;
        if (cn < NC) {
            int sn = s + STAGES - 1;
            if (sn >= STAGES) sn -= STAGES;
            load_chunk(cn, sn);
        }
        cpa_commit();

        const uint32_t sA = sbase + s * STAGE_B;
        const uint32_t sB = sA + TILE_B;

        #pragma unroll
        for (int ks = 0; ks < 4; ++ks) {
            uint32_t ah[4][4], bh[4][2];
            const int ar = lane & 15;
            const int ac = ks * 2 + (lane >> 4);
            #pragma unroll
            for (int im = 0; im < 4; im++) {
                uint32_t off = sw_off(wm + im * 16 + ar, ac);
                ldsm_x4(sA + off, ah[im][0], ah[im][1], ah[im][2], ah[im][3]);
            }
            // B: one ldmatrix.x4 covers 2 n-frags (16 rows) for this k16
            const int br = (lane & 7) + ((lane >> 4) << 3);
            const int bc = ks * 2 + ((lane >> 3) & 1);
            #pragma unroll
            for (int half = 0; half < 2; half++) {
                uint32_t off = sw_off(wn + half * 16 + br, bc);
                ldsm_x4(sB + off, bh[2 * half][0], bh[2 * half][1],
                                  bh[2 * half + 1][0], bh[2 * half + 1][1]);
            }
            #pragma unroll
            for (int im = 0; im < 4; im++)
                #pragma unroll
                for (int in = 0; in < 4; in++)
                    mma_f16(acc[im][in], ah[im], bh[in]);
        }
        if (++s == STAGES) s = 0;
    }

    // epilogue: hoist the 8 distinct bias values per thread into registers
    float bs0[4], bs1[4];
    #pragma unroll
    for (int in = 0; in < 4; in++) {
        const int col = n0 + wn + in * 8 + 2 * (lane & 3);
        bs0[in] = bias[(size_t)e * NTOT + col];
        bs1[in] = bias[(size_t)e * NTOT + col + 1];
    }
    const int lrow = wm + (lane >> 2);
    #pragma unroll
    for (int im = 0; im < 4; im++) {
        #pragma unroll
        for (int half = 0; half < 2; half++) {
            const int lr = lrow + im * 16 + half * 8;
            const int mg = m0 + lr;
            if (mg >= cnt) continue;
            #pragma unroll
            for (int in = 0; in < 4; in++) {
                const int col = n0 + wn + in * 8 + 2 * (lane & 3);
                float z0 = acc[im][in][2 * half]     + bs0[in];
                float z1 = acc[im][in][2 * half + 1] + bs1[in];
                if (FIRST) {
                    // swish via single-MUFU tanh: z*sigmoid(z) = z*(0.5*tanh(z/2)+0.5)
                    float w0 = z0 * (0.5f * tanh_ap(0.5f * z0) + 0.5f);
                    float w1 = z1 * (0.5f * tanh_ap(0.5f * z1) + 0.5f);
                    size_t o = ((size_t)(e * T_) + mg) * H_ + col;
                    *(uint32_t*)(g_h + o) = pack_h2(w0, w1);
                } else {
                    size_t o = (size_t)s_tok[lr] * D_ + col;
                    atomicAdd(out + o,     z0);
                    atomicAdd(out + o + 1, z1);
                }
            }
        }
    }
}

// ---------------- launch ----------------
extern "C" void kernel_launch(void* const* d_in, const int* in_sizes, int n_in,
                              void* d_out, int out_size)
{
    const float* x      = (const float*)d_in[0];
    const float* gate_v = (const float*)d_in[1];
    const float* gate_g = (const float*)d_in[2];
    const float* gate_b = (const float*)d_in[3];
    const float* w1_v   = (const float*)d_in[4];
    const float* w1_g   = (const float*)d_in[5];
    const float* b1     = (const float*)d_in[6];
    const float* w2_v   = (const float*)d_in[7];
    const float* w2_g   = (const float*)d_in[8];
    const float* b2     = (const float*)d_in[9];
    float* out = (float*)d_out;

    cudaFuncSetAttribute(gemm_kernel<D_, true>,  cudaFuncAttributeMaxDynamicSharedMemorySize, SMEM_DYN);
    cudaFuncSetAttribute(gemm_kernel<H_, false>, cudaFuncAttributeMaxDynamicSharedMemorySize, SMEM_DYN);

    void* cnt_addr = nullptr;
    cudaGetSymbolAddress(&cnt_addr, g_cnt);
    cudaMemsetAsync(cnt_addr, 0, E_ * sizeof(int));
    cudaMemsetAsync(out, 0, (size_t)out_size * sizeof(float));

    prep_kernel<<<NB_PREP, 256>>>(x, gate_v, gate_g, gate_b, w1_v, w1_g, w2_v, w2_g);

    gemm_kernel<D_, true><<<dim3(H_ / BN, T_ / BM, E_), NT, SMEM_DYN>>>(b1, out);
    gemm_kernel<H_, false><<<dim3(D_ / BN, T_ / BM, E_), NT, SMEM_DYN>>>(b2, out);
}